// round 2
// baseline (speedup 1.0000x reference)
#include <cuda_runtime.h>
#include <math.h>

#define B_   32
#define N_   8191
#define H_   128
#define G_   384      // 3H
#define NC_  640      // 256 (f) + 384 (iou)
#define OUT_STRIDE (33550336)   // B*N*H

typedef unsigned long long ull;

// -------- scratch (device globals; no runtime allocation) --------
__device__ float g_c  [(size_t)B_ * N_ * H_];   // cell state per node (~134 MB)
__device__ float g_wtA[128 * 384];              // W_iou transposed  [k][g]
__device__ float g_wtC[256 * 640];              // (U_f_w | U_iou) transposed [k][c]

// -------- helpers --------
__device__ __forceinline__ ull pack2(float lo, float hi) {
    ull r; asm("mov.b64 %0, {%1,%2};" : "=l"(r) : "f"(lo), "f"(hi)); return r;
}
__device__ __forceinline__ void unpack2(ull v, float& lo, float& hi) {
    asm("mov.b64 {%0,%1}, %2;" : "=f"(lo), "=f"(hi) : "l"(v));
}
__device__ __forceinline__ void fma2(ull& d, ull a, ull b) {
    asm("fma.rn.f32x2 %0, %1, %2, %0;" : "+l"(d) : "l"(a), "l"(b));
}
__device__ __forceinline__ float sigm(float x) { return 1.0f / (1.0f + expf(-x)); }

// -------- weight transpose (runs every call; deterministic) --------
__global__ void k_transpose(const float* __restrict__ W_iou,
                            const float* __restrict__ U_f_w,
                            const float* __restrict__ U_iou) {
    int idx = blockIdx.x * blockDim.x + threadIdx.x;
    if (idx < 128 * 384) {
        int k = idx / 384, g = idx % 384;
        g_wtA[idx] = W_iou[g * 128 + k];
    }
    if (idx < 256 * 640) {
        int k = idx / 640, c = idx % 640;
        g_wtC[idx] = (c < 256) ? U_f_w[c * 256 + k] : U_iou[(c - 256) * 256 + k];
    }
}

// -------- leaf level (l = 12): fused  x @ W_iou^T  + LSTM (no reduce) --------
// 16 rows/block, 128 threads, 3 cols/thread, f32x2 row-pair accumulators.
__global__ void __launch_bounds__(128) k_leafg(const float* __restrict__ x,
                                               const float* __restrict__ b_iou,
                                               float* __restrict__ out) {
    __shared__ __align__(16) float smem[16 * G_];   // 24 KB: stage xs then results
    const int tid = threadIdx.x;
    const int m0  = blockIdx.x * 16;                // row tile (m = b*4096 + j)

    // ---- stage x tile (16 rows x 128) as [k][r] into first 8 KB ----
    float* xs = smem;
    {
        int b = m0 >> 12, j = m0 & 4095;            // tile never crosses batch (4096%16==0)
        const float* rowbase = x + ((size_t)b * N_ + 4095 + j) * H_;
        for (int t = tid; t < 512; t += 128) {
            int r = t & 15, kq = t >> 4;
            float4 v = *reinterpret_cast<const float4*>(rowbase + r * 128 + kq * 4);
            xs[(4 * kq + 0) * 16 + r] = v.x;
            xs[(4 * kq + 1) * 16 + r] = v.y;
            xs[(4 * kq + 2) * 16 + r] = v.z;
            xs[(4 * kq + 3) * 16 + r] = v.w;
        }
    }
    __syncthreads();

    const int c0 = tid, c1 = tid + 128, c2 = tid + 256;
    ull acc0[8], acc1[8], acc2[8];
#pragma unroll
    for (int p = 0; p < 8; p++) { acc0[p] = 0ull; acc1[p] = 0ull; acc2[p] = 0ull; }

    const ull* xs2 = reinterpret_cast<const ull*>(xs);
#pragma unroll 4
    for (int k = 0; k < 128; k++) {
        float w0 = g_wtA[k * G_ + c0];
        float w1 = g_wtA[k * G_ + c1];
        float w2 = g_wtA[k * G_ + c2];
        ull b0 = pack2(w0, w0), b1 = pack2(w1, w1), b2 = pack2(w2, w2);
#pragma unroll
        for (int p = 0; p < 8; p++) {
            ull a = xs2[k * 8 + p];
            fma2(acc0[p], a, b0);
            fma2(acc1[p], a, b1);
            fma2(acc2[p], a, b2);
        }
    }
    __syncthreads();                                 // xs no longer needed

    // ---- stage results [r][384] ----
#pragma unroll
    for (int p = 0; p < 8; p++) {
        float lo, hi;
        unpack2(acc0[p], lo, hi);
        smem[(2 * p) * G_ + c0] = lo;  smem[(2 * p + 1) * G_ + c0] = hi;
        unpack2(acc1[p], lo, hi);
        smem[(2 * p) * G_ + c1] = lo;  smem[(2 * p + 1) * G_ + c1] = hi;
        unpack2(acc2[p], lo, hi);
        smem[(2 * p) * G_ + c2] = lo;  smem[(2 * p + 1) * G_ + c2] = hi;
    }
    __syncthreads();

    // ---- epilogue: 16 rows x 128 hidden ----
    for (int idx = tid; idx < 16 * 128; idx += 128) {
        int r  = idx >> 7;
        int hh = idx & 127;
        int m = m0 + r;
        int b = m >> 12, j = m & 4095;
        size_t ib = (size_t)b * N_ + 4095 + j;
        float i = smem[r * G_ + hh]       + b_iou[hh];
        float o = smem[r * G_ + 128 + hh] + b_iou[128 + hh];
        float u = smem[r * G_ + 256 + hh] + b_iou[256 + hh];
        float c = sigm(i) * tanhf(u);
        float h = sigm(o) * tanhf(c);
        g_c[ib * H_ + hh] = c;
        out[ib * H_ + hh] = h;
        out[OUT_STRIDE + ib * H_ + hh] = h;
    }
}

// -------- fused internal level --------
// [M,256] @ (U_f_w|U_iou)^T  +  [M,128] @ W_iou^T (iou cols only)  + LSTM epilogue.
// 16 rows/block, 320 threads, 2 cols/thread, f32x2 row-pair accumulators.
__global__ void __launch_bounds__(320) k_level(const float* __restrict__ x,
                                               const float* __restrict__ b_iou,
                                               const float* __restrict__ U_f_b,
                                               float* __restrict__ out,
                                               int lshift) {
    __shared__ __align__(16) float smem[16 * NC_];   // 40 KB
    const int tid = threadIdx.x;
    const int n_l = 1 << lshift;
    const int lo  = n_l - 1;         // first heap index of this level
    const int loc = 2 * n_l - 1;     // first heap index of child level
    const int m0  = blockIdx.x * 16;

    float* hs = smem;                // 16 KB: h_cat [k][r], k in [0,256)
    float* xs = smem + 256 * 16;     //  8 KB: x     [k][r], k in [0,128)

    // ---- stage h_cat (16 x 256) ----
    for (int t = tid; t < 16 * 64; t += 320) {
        int r = t & 15, kq = t >> 4;
        int m = m0 + r;
        int b = m >> lshift, j = m & (n_l - 1);
        const float* src = out + ((size_t)b * N_ + loc + 2 * j) * H_;  // 256 contiguous
        float4 v = *reinterpret_cast<const float4*>(src + kq * 4);
        hs[(4 * kq + 0) * 16 + r] = v.x;
        hs[(4 * kq + 1) * 16 + r] = v.y;
        hs[(4 * kq + 2) * 16 + r] = v.z;
        hs[(4 * kq + 3) * 16 + r] = v.w;
    }
    // ---- stage x (16 x 128) ----
    for (int t = tid; t < 16 * 32; t += 320) {
        int r = t & 15, kq = t >> 4;
        int m = m0 + r;
        int b = m >> lshift, j = m & (n_l - 1);
        const float* src = x + ((size_t)b * N_ + lo + j) * H_;
        float4 v = *reinterpret_cast<const float4*>(src + kq * 4);
        xs[(4 * kq + 0) * 16 + r] = v.x;
        xs[(4 * kq + 1) * 16 + r] = v.y;
        xs[(4 * kq + 2) * 16 + r] = v.z;
        xs[(4 * kq + 3) * 16 + r] = v.w;
    }
    __syncthreads();

    const int c0 = tid, c1 = tid + 320;
    ull acc0[8], acc1[8];
#pragma unroll
    for (int p = 0; p < 8; p++) { acc0[p] = 0ull; acc1[p] = 0ull; }

    // ---- phase 1: h_cat against (U_f_w | U_iou), K = 256, all 640 cols ----
    const ull* hs2 = reinterpret_cast<const ull*>(hs);
#pragma unroll 4
    for (int k = 0; k < 256; k++) {
        float w0 = g_wtC[k * NC_ + c0];
        float w1 = g_wtC[k * NC_ + c1];
        ull b0 = pack2(w0, w0), b1 = pack2(w1, w1);
#pragma unroll
        for (int p = 0; p < 8; p++) {
            ull a = hs2[k * 8 + p];
            fma2(acc0[p], a, b0);
            fma2(acc1[p], a, b1);
        }
    }
    // ---- phase 2: x against W_iou, K = 128, iou cols (c >= 256) only ----
    const ull* xs2 = reinterpret_cast<const ull*>(xs);
    if (tid >= 256) {           // warps 8,9: c0 in [256,320) participates too
#pragma unroll 4
        for (int k = 0; k < 128; k++) {
            float w0 = g_wtA[k * G_ + (c0 - 256)];
            float w1 = g_wtA[k * G_ + (c1 - 256)];
            ull b0 = pack2(w0, w0), b1 = pack2(w1, w1);
#pragma unroll
            for (int p = 0; p < 8; p++) {
                ull a = xs2[k * 8 + p];
                fma2(acc0[p], a, b0);
                fma2(acc1[p], a, b1);
            }
        }
    } else {                    // c1 = tid+320 >= 320 >= 256 always participates
#pragma unroll 4
        for (int k = 0; k < 128; k++) {
            float w1 = g_wtA[k * G_ + (c1 - 256)];
            ull b1 = pack2(w1, w1);
#pragma unroll
            for (int p = 0; p < 8; p++) {
                ull a = xs2[k * 8 + p];
                fma2(acc1[p], a, b1);
            }
        }
    }
    __syncthreads();   // done reading hs/xs; smem becomes result stage [r][640]

#pragma unroll
    for (int p = 0; p < 8; p++) {
        float lo0, hi0, lo1, hi1;
        unpack2(acc0[p], lo0, hi0);
        unpack2(acc1[p], lo1, hi1);
        smem[(2 * p) * NC_ + c0]     = lo0;
        smem[(2 * p + 1) * NC_ + c0] = hi0;
        smem[(2 * p) * NC_ + c1]     = lo1;
        smem[(2 * p + 1) * NC_ + c1] = hi1;
    }
    __syncthreads();

    // ---- epilogue: 16 rows x 128 hidden ----
    for (int idx = tid; idx < 16 * 128; idx += 320) {
        int r  = idx >> 7;
        int hh = idx & 127;
        int m = m0 + r;
        int b = m >> lshift, j = m & (n_l - 1);
        size_t ib  = (size_t)b * N_ + lo + j;
        size_t ibc = (size_t)b * N_ + loc + 2 * j;   // child 0

        float f0 = sigm(smem[r * NC_ + hh]       + U_f_b[hh]);
        float f1 = sigm(smem[r * NC_ + 128 + hh] + U_f_b[128 + hh]);
        float cred = f0 * g_c[ibc * H_ + hh] + f1 * g_c[(ibc + 1) * H_ + hh];

        float i = smem[r * NC_ + 256 + hh] + b_iou[hh];
        float o = smem[r * NC_ + 384 + hh] + b_iou[128 + hh];
        float u = smem[r * NC_ + 512 + hh] + b_iou[256 + hh];

        float c = sigm(i) * tanhf(u) + cred;
        float h = sigm(o) * tanhf(c);
        g_c[ib * H_ + hh] = c;
        out[ib * H_ + hh] = h;
        out[OUT_STRIDE + ib * H_ + hh] = h;
    }
}

// -------- launch --------
extern "C" void kernel_launch(void* const* d_in, const int* in_sizes, int n_in,
                              void* d_out, int out_size) {
    (void)in_sizes; (void)n_in; (void)out_size;
    const float* x     = (const float*)d_in[0];
    const float* W_iou = (const float*)d_in[1];
    const float* U_iou = (const float*)d_in[2];
    const float* b_iou = (const float*)d_in[3];
    const float* U_f_w = (const float*)d_in[4];
    const float* U_f_b = (const float*)d_in[5];
    float* out = (float*)d_out;

    k_transpose<<<(256 * 640 + 255) / 256, 256>>>(W_iou, U_f_w, U_iou);

    // leaves: 32 * 4096 rows / 16 = 8192 blocks (fused x-GEMM + LSTM)
    k_leafg<<<8192, 128>>>(x, b_iou, out);

    // internal levels, bottom-up (serialized on stream)
    for (int l = 11; l >= 0; --l) {
        int blocks = (32 << l) / 16;
        k_level<<<blocks, 320>>>(x, b_iou, U_f_b, out, l);
    }
}

// round 4
// speedup vs baseline: 1.6141x; 1.6141x over previous
#include <cuda_runtime.h>
#include <cstdint>
#include <math.h>

#define B_   32
#define N_   8191
#define H_   128
#define OUT_STRIDE 33550336   // B*N*H

// -------- device scratch (no runtime allocation) --------
__device__ float g_c[(size_t)B_ * N_ * H_];   // cell states (~134 MB)
__device__ float g_wB[48 * 80 * 64];          // level weights, frag-ready [kb][nb][lane][2]
__device__ float g_wA[16 * 48 * 64];          // leaf  weights, frag-ready [kb][nb][lane][2]

// -------- helpers --------
__device__ __forceinline__ uint32_t tf32r(float f) {
    uint32_t r; asm("cvt.rna.tf32.f32 %0, %1;" : "=r"(r) : "f"(f)); return r;
}
__device__ __forceinline__ float sigm(float x) { return 1.0f / (1.0f + expf(-x)); }

__device__ __forceinline__ void mma8(float c[4], uint32_t a0, uint32_t a1, uint32_t a2,
                                     uint32_t a3, uint32_t b0, uint32_t b1) {
    asm volatile("mma.sync.aligned.m16n8k8.row.col.f32.tf32.tf32.f32 "
                 "{%0,%1,%2,%3}, {%4,%5,%6,%7}, {%8,%9}, {%0,%1,%2,%3};"
                 : "+f"(c[0]), "+f"(c[1]), "+f"(c[2]), "+f"(c[3])
                 : "r"(a0), "r"(a1), "r"(a2), "r"(a3), "r"(b0), "r"(b1));
}

// -------- weight prep: fragment-ready, tf32-rounded --------
// g_wB: K=384 (48 kb) x 640 cols (80 nb). k<256: (U_f_w | U_iou); k>=256: (0 | W_iou).
// g_wA: K=128 (16 kb) x 384 cols (48 nb): W_iou.
__global__ void k_prep(const float* __restrict__ W_iou,
                       const float* __restrict__ U_iou,
                       const float* __restrict__ U_f_w) {
    int idx = blockIdx.x * blockDim.x + threadIdx.x;
    if (idx < 48 * 80 * 64) {
        int kb = idx / 5120, rem = idx % 5120;
        int nb = rem / 64, r2 = rem % 64;
        int lane = r2 >> 1, j = r2 & 1;
        int k = kb * 8 + (lane & 3) + 4 * j;
        int c = nb * 8 + (lane >> 2);
        float v;
        if (k < 256) v = (c < 256) ? U_f_w[c * 256 + k] : U_iou[(c - 256) * 256 + k];
        else         v = (c >= 256) ? W_iou[(c - 256) * 128 + (k - 256)] : 0.0f;
        g_wB[idx] = __uint_as_float(tf32r(v));
    }
    int idx2 = idx - 48 * 80 * 64;
    if (idx2 >= 0 && idx2 < 16 * 48 * 64) {
        int kb = idx2 / 3072, rem = idx2 % 3072;
        int nb = rem / 64, r2 = rem % 64;
        int lane = r2 >> 1, j = r2 & 1;
        int k = kb * 8 + (lane & 3) + 4 * j;
        int g = nb * 8 + (lane >> 2);
        g_wA[idx2] = __uint_as_float(tf32r(W_iou[g * 128 + k]));
    }
}

// stage one float4 (4 consecutive k) of row r into frag-major smem
__device__ __forceinline__ void stageA(float* sm, int nkb, int r, int q, float4 v) {
    int k0 = q * 4;
    int rb16 = r >> 4, rr = r & 15, rlo = rr & 7, rhi = rr >> 3;
    int kb = k0 >> 3, khi = (k0 >> 2) & 1;
    int jj = rhi + 2 * khi;
    float* dst = sm + (((rb16 * nkb + kb) * 32 + rlo * 4) * 4 + jj);
    dst[0]  = __uint_as_float(tf32r(v.x));
    dst[4]  = __uint_as_float(tf32r(v.y));
    dst[8]  = __uint_as_float(tf32r(v.z));
    dst[12] = __uint_as_float(tf32r(v.w));
}

// ===================== leaf kernel: [64,128] @ [384,128]^T + LSTM =====================
// 384 threads = 12 warps: cq = w%6 (64 cols = 8 nb), rbp = w/6 (32 rows = 2 m16 tiles)
#define LEAF_CS 392    // padded C row stride
__global__ void __launch_bounds__(384) k_leaf(const float* __restrict__ x,
                                              const float* __restrict__ b_iou,
                                              float* __restrict__ out) {
    extern __shared__ float sm[];
    const int tid = threadIdx.x, lane = tid & 31, warp = tid >> 5;
    const int m0 = blockIdx.x * 64;

    // stage A (64 x 128): 64 rows x 32 float4
    for (int t = tid; t < 64 * 32; t += 384) {
        int r = t >> 5, q = t & 31;
        int m = m0 + r;
        int b = m >> 12, j = m & 4095;
        float4 v = *reinterpret_cast<const float4*>(
            x + ((size_t)b * N_ + 4095 + j) * H_ + q * 4);
        stageA(sm, 16, r, q, v);
    }
    __syncthreads();

    const int cq = warp % 6, rbp = warp / 6;
    const int rb0 = rbp * 2, rb1 = rbp * 2 + 1;
    float acc[8][2][4];
#pragma unroll
    for (int i = 0; i < 8; i++)
#pragma unroll
        for (int t = 0; t < 2; t++)
#pragma unroll
            for (int q = 0; q < 4; q++) acc[i][t][q] = 0.0f;

    const uint4* sA4 = reinterpret_cast<const uint4*>(sm);
    const uint2* wB = reinterpret_cast<const uint2*>(g_wA);
    for (int kb = 0; kb < 16; kb++) {
        uint4 A0 = sA4[(rb0 * 16 + kb) * 32 + lane];
        uint4 A1 = sA4[(rb1 * 16 + kb) * 32 + lane];
#pragma unroll
        for (int i = 0; i < 8; i++) {
            int nb = cq * 8 + i;
            uint2 Bv = wB[(kb * 48 + nb) * 32 + lane];
            mma8(acc[i][0], A0.x, A0.y, A0.z, A0.w, Bv.x, Bv.y);
            mma8(acc[i][1], A1.x, A1.y, A1.z, A1.w, Bv.x, Bv.y);
        }
    }
    __syncthreads();   // reuse smem as C [64][LEAF_CS]

#pragma unroll
    for (int i = 0; i < 8; i++) {
        int colb = (cq * 8 + i) * 8 + (lane & 3) * 2;
#pragma unroll
        for (int t = 0; t < 2; t++) {
            int r0 = rbp * 32 + t * 16 + (lane >> 2);
            *reinterpret_cast<float2*>(sm + r0 * LEAF_CS + colb) =
                make_float2(acc[i][t][0], acc[i][t][1]);
            *reinterpret_cast<float2*>(sm + (r0 + 8) * LEAF_CS + colb) =
                make_float2(acc[i][t][2], acc[i][t][3]);
        }
    }
    __syncthreads();

    for (int t = tid; t < 64 * 128; t += 384) {
        int r = t >> 7, hh = t & 127;
        int m = m0 + r;
        int b = m >> 12, j = m & 4095;
        size_t ib = (size_t)b * N_ + 4095 + j;
        const float* Cr = sm + r * LEAF_CS;
        float i_ = Cr[hh]       + b_iou[hh];
        float o_ = Cr[128 + hh] + b_iou[128 + hh];
        float u_ = Cr[256 + hh] + b_iou[256 + hh];
        float c = sigm(i_) * tanhf(u_);
        float h = sigm(o_) * tanhf(c);
        g_c[ib * H_ + hh] = c;
        out[ib * H_ + hh] = h;
        out[OUT_STRIDE + ib * H_ + hh] = h;
    }
}

// ===================== level kernel: [64,384] @ [640,384]^T + LSTM =====================
// 512 threads = 16 warps: cq = w%8 (80 cols = 10 nb), rbp = w/8 (32 rows)
#define LVL_CS 648     // padded C row stride
__global__ void __launch_bounds__(512) k_level(const float* __restrict__ x,
                                               const float* __restrict__ b_iou,
                                               const float* __restrict__ U_f_b,
                                               float* __restrict__ out,
                                               int lshift) {
    extern __shared__ float sm[];
    const int tid = threadIdx.x, lane = tid & 31, warp = tid >> 5;
    const int n_l = 1 << lshift, lo = n_l - 1, loc = 2 * n_l - 1;
    const int rows_l = 32 << lshift;
    const int m0 = blockIdx.x * 64;

    // stage A (64 x 384): k<256 = children h (256 contiguous), k>=256 = x row
    for (int t = tid; t < 64 * 96; t += 512) {
        int r = t / 96, q = t % 96;
        int m = m0 + r;
        float4 v = make_float4(0.f, 0.f, 0.f, 0.f);
        if (m < rows_l) {
            int b = m >> lshift, j = m & (n_l - 1);
            const float* src = (q < 64)
                ? out + ((size_t)b * N_ + loc + 2 * j) * H_ + q * 4
                : x + ((size_t)b * N_ + lo + j) * H_ + (q - 64) * 4;
            v = *reinterpret_cast<const float4*>(src);
        }
        stageA(sm, 48, r, q, v);
    }
    __syncthreads();

    const int cq = warp & 7, rbp = warp >> 3;
    const int rb0 = rbp * 2, rb1 = rbp * 2 + 1;
    float acc[10][2][4];
#pragma unroll
    for (int i = 0; i < 10; i++)
#pragma unroll
        for (int t = 0; t < 2; t++)
#pragma unroll
            for (int q = 0; q < 4; q++) acc[i][t][q] = 0.0f;

    const uint4* sA4 = reinterpret_cast<const uint4*>(sm);
    const uint2* wB = reinterpret_cast<const uint2*>(g_wB);
    for (int kb = 0; kb < 48; kb++) {
        uint4 A0 = sA4[(rb0 * 48 + kb) * 32 + lane];
        uint4 A1 = sA4[(rb1 * 48 + kb) * 32 + lane];
#pragma unroll
        for (int i = 0; i < 10; i++) {
            int nb = cq * 10 + i;
            uint2 Bv = wB[(kb * 80 + nb) * 32 + lane];
            mma8(acc[i][0], A0.x, A0.y, A0.z, A0.w, Bv.x, Bv.y);
            mma8(acc[i][1], A1.x, A1.y, A1.z, A1.w, Bv.x, Bv.y);
        }
    }
    __syncthreads();   // reuse smem as C [64][LVL_CS]

#pragma unroll
    for (int i = 0; i < 10; i++) {
        int colb = (cq * 10 + i) * 8 + (lane & 3) * 2;
#pragma unroll
        for (int t = 0; t < 2; t++) {
            int r0 = rbp * 32 + t * 16 + (lane >> 2);
            *reinterpret_cast<float2*>(sm + r0 * LVL_CS + colb) =
                make_float2(acc[i][t][0], acc[i][t][1]);
            *reinterpret_cast<float2*>(sm + (r0 + 8) * LVL_CS + colb) =
                make_float2(acc[i][t][2], acc[i][t][3]);
        }
    }
    __syncthreads();

    // epilogue: C cols [0,256)=f_pre, [256,640)=iou
    for (int t = tid; t < 64 * 128; t += 512) {
        int r = t >> 7, hh = t & 127;
        int m = m0 + r;
        if (m < rows_l) {
            int b = m >> lshift, j = m & (n_l - 1);
            size_t ib  = (size_t)b * N_ + lo + j;
            size_t ibc = (size_t)b * N_ + loc + 2 * j;
            const float* Cr = sm + r * LVL_CS;
            float f0 = sigm(Cr[hh]       + U_f_b[hh]);
            float f1 = sigm(Cr[128 + hh] + U_f_b[128 + hh]);
            float cred = f0 * g_c[ibc * H_ + hh] + f1 * g_c[(ibc + 1) * H_ + hh];
            float i_ = Cr[256 + hh] + b_iou[hh];
            float o_ = Cr[384 + hh] + b_iou[128 + hh];
            float u_ = Cr[512 + hh] + b_iou[256 + hh];
            float c = sigm(i_) * tanhf(u_) + cred;
            float h = sigm(o_) * tanhf(c);
            g_c[ib * H_ + hh] = c;
            out[ib * H_ + hh] = h;
            out[OUT_STRIDE + ib * H_ + hh] = h;
        }
    }
}

// -------- launch --------
extern "C" void kernel_launch(void* const* d_in, const int* in_sizes, int n_in,
                              void* d_out, int out_size) {
    (void)in_sizes; (void)n_in; (void)out_size;
    const float* x     = (const float*)d_in[0];
    const float* W_iou = (const float*)d_in[1];
    const float* U_iou = (const float*)d_in[2];
    const float* b_iou = (const float*)d_in[3];
    const float* U_f_w = (const float*)d_in[4];
    const float* U_f_b = (const float*)d_in[5];
    float* out = (float*)d_out;

    cudaFuncSetAttribute(k_level, cudaFuncAttributeMaxDynamicSharedMemorySize,
                         64 * LVL_CS * 4);
    cudaFuncSetAttribute(k_leaf, cudaFuncAttributeMaxDynamicSharedMemorySize,
                         64 * LEAF_CS * 4);

    k_prep<<<1152, 256>>>(W_iou, U_iou, U_f_w);

    // leaves: 131072 rows / 64
    k_leaf<<<2048, 384, 64 * LEAF_CS * 4>>>(x, b_iou, out);

    // internal levels bottom-up
    for (int l = 11; l >= 0; --l) {
        int rows = 32 << l;
        int blocks = (rows + 63) / 64;
        k_level<<<blocks, 512, 64 * LVL_CS * 4>>>(x, b_iou, U_f_b, out, l);
    }
}

// round 5
// speedup vs baseline: 1.7521x; 1.0855x over previous
#include <cuda_runtime.h>
#include <cstdint>
#include <math.h>

#define B_   32
#define N_   8191
#define H_   128
#define OUT_STRIDE 33550336   // B*N*H

// -------- device scratch (no runtime allocation) --------
__device__ float g_c[(size_t)B_ * N_ * H_];   // cell states (~134 MB)
__device__ float g_wB[48 * 80 * 64];          // level weights, frag-ready [kb][nb][lane][2]
__device__ float g_wA[16 * 48 * 64];          // leaf  weights, frag-ready [kb][nb][lane][2]

// -------- helpers --------
__device__ __forceinline__ uint32_t tf32r(float f) {
    uint32_t r; asm("cvt.rna.tf32.f32 %0, %1;" : "=r"(r) : "f"(f)); return r;
}
__device__ __forceinline__ float sigm(float x) { return 1.0f / (1.0f + expf(-x)); }

__device__ __forceinline__ void mma8(float c[4], uint32_t a0, uint32_t a1, uint32_t a2,
                                     uint32_t a3, uint32_t b0, uint32_t b1) {
    asm volatile("mma.sync.aligned.m16n8k8.row.col.f32.tf32.tf32.f32 "
                 "{%0,%1,%2,%3}, {%4,%5,%6,%7}, {%8,%9}, {%0,%1,%2,%3};"
                 : "+f"(c[0]), "+f"(c[1]), "+f"(c[2]), "+f"(c[3])
                 : "r"(a0), "r"(a1), "r"(a2), "r"(a3), "r"(b0), "r"(b1));
}

// -------- weight prep: fragment-ready, tf32-rounded --------
__global__ void k_prep(const float* __restrict__ W_iou,
                       const float* __restrict__ U_iou,
                       const float* __restrict__ U_f_w) {
    int idx = blockIdx.x * blockDim.x + threadIdx.x;
    if (idx < 48 * 80 * 64) {
        int kb = idx / 5120, rem = idx % 5120;
        int nb = rem / 64, r2 = rem % 64;
        int lane = r2 >> 1, j = r2 & 1;
        int k = kb * 8 + (lane & 3) + 4 * j;
        int c = nb * 8 + (lane >> 2);
        float v;
        if (k < 256) v = (c < 256) ? U_f_w[c * 256 + k] : U_iou[(c - 256) * 256 + k];
        else         v = (c >= 256) ? W_iou[(c - 256) * 128 + (k - 256)] : 0.0f;
        g_wB[idx] = __uint_as_float(tf32r(v));
    }
    int idx2 = idx - 48 * 80 * 64;
    if (idx2 >= 0 && idx2 < 16 * 48 * 64) {
        int kb = idx2 / 3072, rem = idx2 % 3072;
        int nb = rem / 64, r2 = rem % 64;
        int lane = r2 >> 1, j = r2 & 1;
        int k = kb * 8 + (lane & 3) + 4 * j;
        int g = nb * 8 + (lane >> 2);
        g_wA[idx2] = __uint_as_float(tf32r(W_iou[g * 128 + k]));
    }
}

// stage one float4 (4 consecutive k) of row r into frag-major smem
__device__ __forceinline__ void stageA(float* sm, int nkb, int r, int q, float4 v) {
    int k0 = q * 4;
    int rb16 = r >> 4, rr = r & 15, rlo = rr & 7, rhi = rr >> 3;
    int kb = k0 >> 3, khi = (k0 >> 2) & 1;
    int jj = rhi + 2 * khi;
    float* dst = sm + (((rb16 * nkb + kb) * 32 + rlo * 4) * 4 + jj);
    dst[0]  = __uint_as_float(tf32r(v.x));
    dst[4]  = __uint_as_float(tf32r(v.y));
    dst[8]  = __uint_as_float(tf32r(v.z));
    dst[12] = __uint_as_float(tf32r(v.w));
}

// ===================== leaf kernel: [64,128] @ [384,128]^T + LSTM =====================
// 384 threads = 12 warps; warp owns 4 nb cols x all 4 row-tiles. B prefetched.
#define LEAF_CS 392
__global__ void __launch_bounds__(384) k_leaf(const float* __restrict__ x,
                                              const float* __restrict__ b_iou,
                                              float* __restrict__ out) {
    extern __shared__ float sm[];
    const int tid = threadIdx.x, lane = tid & 31, warp = tid >> 5;
    const int m0 = blockIdx.x * 64;

    for (int t = tid; t < 64 * 32; t += 384) {
        int r = t >> 5, q = t & 31;
        int m = m0 + r;
        int b = m >> 12, j = m & 4095;
        float4 v = *reinterpret_cast<const float4*>(
            x + ((size_t)b * N_ + 4095 + j) * H_ + q * 4);
        stageA(sm, 16, r, q, v);
    }
    __syncthreads();

    float acc[4][4][4];
#pragma unroll
    for (int i = 0; i < 4; i++)
#pragma unroll
        for (int rb = 0; rb < 4; rb++)
#pragma unroll
            for (int q = 0; q < 4; q++) acc[i][rb][q] = 0.0f;

    const uint4* sA4 = reinterpret_cast<const uint4*>(sm);
    const uint2* wB = reinterpret_cast<const uint2*>(g_wA);
    const int nb0 = warp * 4;

    uint2 Bc[4], Bn[4];
#pragma unroll
    for (int i = 0; i < 4; i++) Bc[i] = wB[(0 * 48 + nb0 + i) * 32 + lane];

    for (int kb = 0; kb < 16; kb++) {
        if (kb < 15) {
#pragma unroll
            for (int i = 0; i < 4; i++) Bn[i] = wB[((kb + 1) * 48 + nb0 + i) * 32 + lane];
        }
        uint4 A[4];
#pragma unroll
        for (int rb = 0; rb < 4; rb++) A[rb] = sA4[(rb * 16 + kb) * 32 + lane];
#pragma unroll
        for (int i = 0; i < 4; i++)
#pragma unroll
            for (int rb = 0; rb < 4; rb++)
                mma8(acc[i][rb], A[rb].x, A[rb].y, A[rb].z, A[rb].w, Bc[i].x, Bc[i].y);
#pragma unroll
        for (int i = 0; i < 4; i++) Bc[i] = Bn[i];
    }
    __syncthreads();   // smem becomes C [64][LEAF_CS]

#pragma unroll
    for (int i = 0; i < 4; i++) {
        int colb = (nb0 + i) * 8 + (lane & 3) * 2;
#pragma unroll
        for (int rb = 0; rb < 4; rb++) {
            int r0 = rb * 16 + (lane >> 2);
            *reinterpret_cast<float2*>(sm + r0 * LEAF_CS + colb) =
                make_float2(acc[i][rb][0], acc[i][rb][1]);
            *reinterpret_cast<float2*>(sm + (r0 + 8) * LEAF_CS + colb) =
                make_float2(acc[i][rb][2], acc[i][rb][3]);
        }
    }
    __syncthreads();

    for (int t = tid; t < 64 * 128; t += 384) {
        int r = t >> 7, hh = t & 127;
        int m = m0 + r;
        int b = m >> 12, j = m & 4095;
        size_t ib = (size_t)b * N_ + 4095 + j;
        const float* Cr = sm + r * LEAF_CS;
        float i_ = Cr[hh]       + b_iou[hh];
        float o_ = Cr[128 + hh] + b_iou[128 + hh];
        float u_ = Cr[256 + hh] + b_iou[256 + hh];
        float c = sigm(i_) * tanhf(u_);
        float h = sigm(o_) * tanhf(c);
        g_c[ib * H_ + hh] = c;
        out[ib * H_ + hh] = h;
        out[OUT_STRIDE + ib * H_ + hh] = h;
    }
}

// ===================== level kernel: [64,384] @ [640,384]^T + LSTM =====================
// 512 threads = 16 warps; warp owns 5 nb cols x all 4 row-tiles. B prefetched.
#define LVL_CS 648
__global__ void __launch_bounds__(512) k_level(const float* __restrict__ x,
                                               const float* __restrict__ b_iou,
                                               const float* __restrict__ U_f_b,
                                               float* __restrict__ out,
                                               int lshift) {
    extern __shared__ float sm[];
    const int tid = threadIdx.x, lane = tid & 31, warp = tid >> 5;
    const int n_l = 1 << lshift, lo = n_l - 1, loc = 2 * n_l - 1;
    const int rows_l = 32 << lshift;
    const int m0 = blockIdx.x * 64;

    for (int t = tid; t < 64 * 96; t += 512) {
        int r = t / 96, q = t % 96;
        int m = m0 + r;
        float4 v = make_float4(0.f, 0.f, 0.f, 0.f);
        if (m < rows_l) {
            int b = m >> lshift, j = m & (n_l - 1);
            const float* src = (q < 64)
                ? out + ((size_t)b * N_ + loc + 2 * j) * H_ + q * 4
                : x + ((size_t)b * N_ + lo + j) * H_ + (q - 64) * 4;
            v = *reinterpret_cast<const float4*>(src);
        }
        stageA(sm, 48, r, q, v);
    }
    __syncthreads();

    float acc[5][4][4];
#pragma unroll
    for (int i = 0; i < 5; i++)
#pragma unroll
        for (int rb = 0; rb < 4; rb++)
#pragma unroll
            for (int q = 0; q < 4; q++) acc[i][rb][q] = 0.0f;

    const uint4* sA4 = reinterpret_cast<const uint4*>(sm);
    const uint2* wB = reinterpret_cast<const uint2*>(g_wB);
    const int nb0 = warp * 5;
    // warps 0..5 own cols < 256 (f block) whose weights are zero for kb >= 32
    const int kbmax = (warp < 6) ? 32 : 48;

    uint2 Bc[5], Bn[5];
#pragma unroll
    for (int i = 0; i < 5; i++) Bc[i] = wB[(0 * 80 + nb0 + i) * 32 + lane];

    for (int kb = 0; kb < kbmax; kb++) {
        if (kb + 1 < kbmax) {
#pragma unroll
            for (int i = 0; i < 5; i++) Bn[i] = wB[((kb + 1) * 80 + nb0 + i) * 32 + lane];
        }
        uint4 A[4];
#pragma unroll
        for (int rb = 0; rb < 4; rb++) A[rb] = sA4[(rb * 48 + kb) * 32 + lane];
#pragma unroll
        for (int i = 0; i < 5; i++)
#pragma unroll
            for (int rb = 0; rb < 4; rb++)
                mma8(acc[i][rb], A[rb].x, A[rb].y, A[rb].z, A[rb].w, Bc[i].x, Bc[i].y);
#pragma unroll
        for (int i = 0; i < 5; i++) Bc[i] = Bn[i];
    }
    __syncthreads();   // smem becomes C [64][LVL_CS]

#pragma unroll
    for (int i = 0; i < 5; i++) {
        int colb = (nb0 + i) * 8 + (lane & 3) * 2;
#pragma unroll
        for (int rb = 0; rb < 4; rb++) {
            int r0 = rb * 16 + (lane >> 2);
            *reinterpret_cast<float2*>(sm + r0 * LVL_CS + colb) =
                make_float2(acc[i][rb][0], acc[i][rb][1]);
            *reinterpret_cast<float2*>(sm + (r0 + 8) * LVL_CS + colb) =
                make_float2(acc[i][rb][2], acc[i][rb][3]);
        }
    }
    __syncthreads();

    for (int t = tid; t < 64 * 128; t += 512) {
        int r = t >> 7, hh = t & 127;
        int m = m0 + r;
        if (m < rows_l) {
            int b = m >> lshift, j = m & (n_l - 1);
            size_t ib  = (size_t)b * N_ + lo + j;
            size_t ibc = (size_t)b * N_ + loc + 2 * j;
            const float* Cr = sm + r * LVL_CS;
            float f0 = sigm(Cr[hh]       + U_f_b[hh]);
            float f1 = sigm(Cr[128 + hh] + U_f_b[128 + hh]);
            float cred = f0 * g_c[ibc * H_ + hh] + f1 * g_c[(ibc + 1) * H_ + hh];
            float i_ = Cr[256 + hh] + b_iou[hh];
            float o_ = Cr[384 + hh] + b_iou[128 + hh];
            float u_ = Cr[512 + hh] + b_iou[256 + hh];
            float c = sigm(i_) * tanhf(u_) + cred;
            float h = sigm(o_) * tanhf(c);
            g_c[ib * H_ + hh] = c;
            out[ib * H_ + hh] = h;
            out[OUT_STRIDE + ib * H_ + hh] = h;
        }
    }
}

// -------- launch --------
extern "C" void kernel_launch(void* const* d_in, const int* in_sizes, int n_in,
                              void* d_out, int out_size) {
    (void)in_sizes; (void)n_in; (void)out_size;
    const float* x     = (const float*)d_in[0];
    const float* W_iou = (const float*)d_in[1];
    const float* U_iou = (const float*)d_in[2];
    const float* b_iou = (const float*)d_in[3];
    const float* U_f_w = (const float*)d_in[4];
    const float* U_f_b = (const float*)d_in[5];
    float* out = (float*)d_out;

    cudaFuncSetAttribute(k_level, cudaFuncAttributeMaxDynamicSharedMemorySize,
                         64 * LVL_CS * 4);
    cudaFuncSetAttribute(k_leaf, cudaFuncAttributeMaxDynamicSharedMemorySize,
                         64 * LEAF_CS * 4);

    k_prep<<<1152, 256>>>(W_iou, U_iou, U_f_w);

    k_leaf<<<2048, 384, 64 * LEAF_CS * 4>>>(x, b_iou, out);

    for (int l = 11; l >= 0; --l) {
        int rows = 32 << l;
        int blocks = (rows + 63) / 64;
        k_level<<<blocks, 512, 64 * LVL_CS * 4>>>(x, b_iou, U_f_b, out, l);
    }
}